// round 9
// baseline (speedup 1.0000x reference)
#include <cuda_runtime.h>
#include <cuda_fp16.h>
#include <stdint.h>

#define LP    4
#define ENC   32
#define FEAT  64
#define D3    64
#define KTOT  112          // 96 data + 1 bias col + 15 pad (K chunks: 7)
#define NBLK  296
#define WARPS 8
#define THREADS (WARPS * 32)

typedef unsigned long long u64;

// X rows: 112 fp16 + pad -> stride 240 B (60 words; 60*r mod 32 distinct for r=0..7)
#define XSTRIDE_B 240
// W rows: 64 fp16 + pad -> stride 144 B (36 words; 36*r mod 32 distinct)
#define WSTRIDE_B 144

// ---- smem layout (bytes) ----
#define OFF_W1P  0                                    // 4*16 u64 packed W1 pairs (512)
#define OFF_B1P  512                                  // 16 u64 packed b1 (128)
#define OFF_WM2P 640                                  // 32 u64 packed Wm2 (256)
#define OFF_BM2  896
#define OFF_WH   1280
#define OFF_XH   (OFF_WH + KTOT * WSTRIDE_B)          // +16128 -> 17408
#define SMEM_TOTAL (OFF_XH + THREADS * XSTRIDE_B)     // 17408 + 61440 = 78848

__device__ float g_A[ENC * D3];
__device__ float g_ybias[D3];

// ---------------- helpers ----------------
__device__ __forceinline__ uint32_t smem_u32(const void* p) {
    uint32_t a;
    asm("{ .reg .u64 t; cvta.to.shared.u64 t, %1; cvt.u32.u64 %0, t; }" : "=r"(a) : "l"(p));
    return a;
}
__device__ __forceinline__ u64 pack2(float lo, float hi) {
    u64 r; asm("mov.b64 %0, {%1, %2};" : "=l"(r) : "f"(lo), "f"(hi)); return r;
}
__device__ __forceinline__ void unpack2(float& lo, float& hi, u64 v) {
    asm("mov.b64 {%0, %1}, %2;" : "=f"(lo), "=f"(hi) : "l"(v));
}
__device__ __forceinline__ u64 ffma2(u64 a, u64 b, u64 c) {
    u64 d; asm("fma.rn.f32x2 %0, %1, %2, %3;" : "=l"(d) : "l"(a), "l"(b), "l"(c)); return d;
}
#define LDSM_X4(r0, r1, r2, r3, a) \
    asm volatile("ldmatrix.sync.aligned.m8n8.x4.shared.b16 {%0,%1,%2,%3}, [%4];" \
                 : "=r"(r0), "=r"(r1), "=r"(r2), "=r"(r3) : "r"(a))
#define LDSM_X4_T(r0, r1, r2, r3, a) \
    asm volatile("ldmatrix.sync.aligned.m8n8.x4.trans.shared.b16 {%0,%1,%2,%3}, [%4];" \
                 : "=r"(r0), "=r"(r1), "=r"(r2), "=r"(r3) : "r"(a))
#define MMA16816H(d, a0, a1, a2, a3, b0, b1) \
    asm volatile("mma.sync.aligned.m16n8k16.row.col.f32.f16.f16.f32 " \
                 "{%0,%1,%2,%3}, {%4,%5,%6,%7}, {%8,%9}, {%0,%1,%2,%3};" \
                 : "+f"((d)[0]), "+f"((d)[1]), "+f"((d)[2]), "+f"((d)[3]) \
                 : "r"(a0), "r"(a1), "r"(a2), "r"(a3), "r"(b0), "r"(b1))
#define PREFETCH_L2(p) asm volatile("prefetch.global.L2 [%0];" :: "l"(p))

__device__ __forceinline__ unsigned pack_h2(float a, float b) {
    __half2 h2 = __floats2half2_rn(a, b);
    return *(unsigned*)&h2;
}

// ---------------------------------------------------------------------------
__global__ void prep_kernel(const float* __restrict__ W2,
                            const float* __restrict__ Wm1,
                            const float* __restrict__ b2,
                            const float* __restrict__ bm1) {
    int t = blockIdx.x * blockDim.x + threadIdx.x;
    if (t < ENC * D3) {
        int k = t >> 6, j = t & 63;
        float s = 0.f;
        #pragma unroll
        for (int e = 0; e < ENC; e++)
            s = fmaf(W2[k * ENC + e], Wm1[e * D3 + j], s);
        g_A[t] = s;
    }
    if (t < D3) {
        float s = bm1[t];
        #pragma unroll
        for (int e = 0; e < ENC; e++)
            s = fmaf(b2[e], Wm1[e * D3 + t], s);
        g_ybias[t] = s;
    }
}

// ---------------------------------------------------------------------------
__global__ __launch_bounds__(THREADS, 2)
void neurtw_mma(const float* __restrict__ pos_table,
                const float* __restrict__ node_feat,
                const float* __restrict__ W1,
                const float* __restrict__ b1,
                const float* __restrict__ Wm1,
                const float* __restrict__ Wm2,
                const float* __restrict__ bm2,
                const int*   __restrict__ key_idx,
                const int*   __restrict__ node_idx,
                float* __restrict__ out,
                int nrows, int ntiles) {
    extern __shared__ __align__(128) char smem[];
    const uint32_t sb = smem_u32(smem);
    const int tid = threadIdx.x, wid = tid >> 5, lane = tid & 31;

    u64*   sW1p  = (u64*)(smem + OFF_W1P);    // [4][16] packed col-pairs
    u64*   sb1p  = (u64*)(smem + OFF_B1P);    // [16]
    u64*   sWm2p = (u64*)(smem + OFF_WM2P);   // [32]
    float* sbm2  = (float*)(smem + OFF_BM2);

    if (tid < 32) sWm2p[tid] = pack2(Wm2[2 * tid], Wm2[2 * tid + 1]);
    if (tid >= 32 && tid < 48) { int j = tid - 32; sb1p[j] = pack2(b1[2 * j], b1[2 * j + 1]); }
    if (tid == 48) *sbm2 = bm2[0];
    if (tid >= 64 && tid < 128) {
        int idx = tid - 64, r = idx >> 4, j = idx & 15;
        sW1p[r * 16 + j] = pack2(W1[r * ENC + 2 * j], W1[r * ENC + 2 * j + 1]);
    }

    // stage W fp16: rows 0..31 g_A, 32..95 Wm1, 96 ybias, 97..111 zero
    for (int t = tid; t < KTOT * 64; t += THREADS) {
        int k = t >> 6, n = t & 63;
        float w;
        if (k < ENC)      w = g_A[k * D3 + n];
        else if (k < 96)  w = Wm1[k * D3 + n];
        else if (k == 96) w = g_ybias[n];
        else              w = 0.f;
        *(__half*)(smem + OFF_WH + k * WSTRIDE_B + n * 2) = __float2half_rn(w);
    }
    // one-time X pad init: col 96 = 1.0, cols 97..111 = 0 (own row = tid)
    {
        char* xr = smem + OFF_XH + tid * XSTRIDE_B;
        *(uint4*)(xr + 192) = make_uint4(pack_h2(1.f, 0.f), 0u, 0u, 0u);
        *(uint4*)(xr + 208) = make_uint4(0u, 0u, 0u, 0u);
    }
    __syncthreads();

    // ---- per-lane constant ldmatrix addresses ----
    const int a_row  = (lane & 7) + 8 * ((lane >> 3) & 1);
    const int a_colb = (lane >> 4) * 16;
    const uint32_t xh_base = sb + OFF_XH + (uint32_t)(wid * 32 + a_row) * XSTRIDE_B + a_colb;
    const uint32_t b_off = (uint32_t)(((lane & 7) + 8 * ((lane >> 3) & 1)) * WSTRIDE_B
                                      + (lane >> 4) * 16);
    const uint32_t wh_base = sb + OFF_WH + b_off;

    const int gw0 = blockIdx.x * WARPS + wid;
    const int gwstride = NBLK * WARPS;
    const int g = lane >> 2, q4 = lane & 3;

    int key_c = 0, nid_c = 0;
    if (gw0 < ntiles) {
        int rr = gw0 * 32 + lane; if (rr >= nrows) rr = 0;
        key_c = key_idx[rr]; nid_c = node_idx[rr];
    }

    for (int tile = gw0; tile < ntiles; tile += gwstride) {
        // ========== phase 1a: PE hidden layer (packed f32x2), fp16, STS ==========
        {
            const float4 e4 = *(const float4*)(pos_table + (size_t)key_c * LP);
            const u64 ex = pack2(e4.x, e4.x), ey = pack2(e4.y, e4.y);
            const u64 ez = pack2(e4.z, e4.z), ew = pack2(e4.w, e4.w);
            unsigned hv[16];
            #pragma unroll
            for (int j = 0; j < 16; j++) {
                u64 s = sb1p[j];
                s = ffma2(ex, sW1p[0 * 16 + j], s);
                s = ffma2(ey, sW1p[1 * 16 + j], s);
                s = ffma2(ez, sW1p[2 * 16 + j], s);
                s = ffma2(ew, sW1p[3 * 16 + j], s);
                float lo, hi; unpack2(lo, hi, s);
                hv[j] = pack_h2(fmaxf(lo, 0.f), fmaxf(hi, 0.f));
            }
            char* xh = smem + OFF_XH + (wid * 32 + lane) * XSTRIDE_B;
            #pragma unroll
            for (int c = 0; c < 4; c++)
                *(uint4*)(xh + c * 16) =
                    make_uint4(hv[4*c], hv[4*c+1], hv[4*c+2], hv[4*c+3]);
        }
        // ========== phase 1b: coalesced cooperative feat gather ==========
        {
            const int sub = lane >> 4;        // 0..1
            const int qq  = lane & 15;        // float4 index within row
            #pragma unroll
            for (int i = 0; i < 16; i++) {
                const int riw = 2 * i + sub;
                const int nidr = __shfl_sync(0xffffffffu, nid_c, riw);
                const float4 fv = __ldg((const float4*)(node_feat + (size_t)nidr * FEAT) + qq);
                const int off = (wid * 32 + riw) * XSTRIDE_B + 64 + 8 * qq;
                *(uint2*)(smem + OFF_XH + off) =
                    make_uint2(pack_h2(fv.x, fv.y), pack_h2(fv.z, fv.w));
            }
        }
        __syncwarp();

        // ---- prefetch next tile to L2 ----
        {
            const int nt = tile + gwstride;
            if (nt < ntiles) {
                int rr = nt * 32 + lane; if (rr >= nrows) rr = 0;
                key_c = key_idx[rr]; nid_c = node_idx[rr];
                const char* pp = (const char*)(pos_table + (size_t)key_c * LP);
                const char* fp = (const char*)(node_feat + (size_t)nid_c * FEAT);
                PREFETCH_L2(pp);
                PREFETCH_L2(fp);
                PREFETCH_L2(fp + 128);
            }
        }

        // ========== phase 2: single-pass fp16 MMA, K=112 (bias folded) ==========
        float acc[2][8][4];
        #pragma unroll
        for (int mt = 0; mt < 2; mt++)
            #pragma unroll
            for (int nt = 0; nt < 8; nt++)
                #pragma unroll
                for (int c = 0; c < 4; c++) acc[mt][nt][c] = 0.f;

        #pragma unroll
        for (int kc = 0; kc < 7; kc++) {
            const uint32_t akoff = (uint32_t)(kc * 32);
            const uint32_t bkoff = (uint32_t)(kc * 16 * WSTRIDE_B);
            uint32_t ah[2][4];
            LDSM_X4(ah[0][0], ah[0][1], ah[0][2], ah[0][3], xh_base + akoff);
            LDSM_X4(ah[1][0], ah[1][1], ah[1][2], ah[1][3], xh_base + 16 * XSTRIDE_B + akoff);

            uint32_t bh[8][2];
            #pragma unroll
            for (int ng = 0; ng < 4; ng++) {
                uint32_t r0, r1, r2, r3;
                LDSM_X4_T(r0, r1, r2, r3, wh_base + bkoff + (uint32_t)(ng * 32));
                bh[2*ng][0] = r0; bh[2*ng][1] = r1; bh[2*ng+1][0] = r2; bh[2*ng+1][1] = r3;
            }
            #pragma unroll
            for (int mt = 0; mt < 2; mt++)
                #pragma unroll
                for (int nt = 0; nt < 8; nt++)
                    MMA16816H(acc[mt][nt], ah[mt][0], ah[mt][1], ah[mt][2], ah[mt][3],
                              bh[nt][0], bh[nt][1]);
        }

        // ========== phase 3: relu + Wm2 dot (bias already in acc), reduce ==========
        float zr[4] = {0.f, 0.f, 0.f, 0.f};
        #pragma unroll
        for (int nt = 0; nt < 8; nt++) {
            float w0, w1; unpack2(w0, w1, sWm2p[nt * 4 + q4]);
            #pragma unroll
            for (int mt = 0; mt < 2; mt++) {
                zr[mt*2+0] = fmaf(fmaxf(acc[mt][nt][0], 0.f), w0, zr[mt*2+0]);
                zr[mt*2+0] = fmaf(fmaxf(acc[mt][nt][1], 0.f), w1, zr[mt*2+0]);
                zr[mt*2+1] = fmaf(fmaxf(acc[mt][nt][2], 0.f), w0, zr[mt*2+1]);
                zr[mt*2+1] = fmaf(fmaxf(acc[mt][nt][3], 0.f), w1, zr[mt*2+1]);
            }
        }
        #pragma unroll
        for (int o = 1; o < 4; o <<= 1) {
            #pragma unroll
            for (int r = 0; r < 4; r++)
                zr[r] += __shfl_xor_sync(0xffffffffu, zr[r], o);
        }
        if (q4 == 0) {
            const float bias = *sbm2;
            const int base = tile * 32;
            const int rows[4] = {g, g + 8, 16 + g, 24 + g};
            #pragma unroll
            for (int r = 0; r < 4; r++) {
                int orow = base + rows[r];
                if (orow < nrows) out[orow] = zr[r] + bias;
            }
        }
        __syncwarp();
    }
}

// ---------------------------------------------------------------------------
extern "C" void kernel_launch(void* const* d_in, const int* in_sizes, int n_in,
                              void* d_out, int out_size) {
    const float* pos_table = (const float*)d_in[0];
    const float* node_feat = (const float*)d_in[1];
    const float* W1        = (const float*)d_in[2];
    const float* b1        = (const float*)d_in[3];
    const float* W2        = (const float*)d_in[4];
    const float* b2        = (const float*)d_in[5];
    const float* Wm1       = (const float*)d_in[6];
    const float* bm1       = (const float*)d_in[7];
    const float* Wm2       = (const float*)d_in[8];
    const float* bm2       = (const float*)d_in[9];
    const int*   key_idx   = (const int*)d_in[10];
    const int*   node_idx  = (const int*)d_in[11];
    float* out = (float*)d_out;

    const int nrows  = out_size;
    const int ntiles = (nrows + 31) / 32;

    cudaFuncSetAttribute(neurtw_mma,
                         cudaFuncAttributeMaxDynamicSharedMemorySize, SMEM_TOTAL);

    prep_kernel<<<(ENC * D3 + 255) / 256, 256>>>(W2, Wm1, b2, bm1);

    neurtw_mma<<<NBLK, THREADS, SMEM_TOTAL>>>(pos_table, node_feat, W1, b1, Wm1,
                                              Wm2, bm2, key_idx, node_idx, out,
                                              nrows, ntiles);
}

// round 10
// speedup vs baseline: 1.0501x; 1.0501x over previous
#include <cuda_runtime.h>
#include <cuda_fp16.h>
#include <stdint.h>

#define LP    4
#define ENC   32
#define FEAT  64
#define D3    64
#define NBLK  296
#define WARPS 6
#define THREADS (WARPS * 32)

typedef unsigned long long u64;

// X rows: 96 fp16 + pad -> stride 208 B (52 words; 52*r mod 32 distinct for r=0..7)
#define XSTRIDE_B 208
// W rows: 64 fp16 + pad -> stride 144 B (36 words; 36*r mod 32 distinct)
#define WSTRIDE_B 144
#define RAWF_STRIDE 256

// ---- smem layout (bytes) ----
#define OFF_W1P  0                                     // 64 u64 (512 B)
#define OFF_B1P  512                                   // 16 u64 (128 B)
#define OFF_WM2P 640                                   // 32 u64 (256 B)
#define OFF_YBP  896                                   // 32 u64 (256 B)
#define OFF_BM2  1152
#define OFF_WH   1280                                  // 96*144 = 13824
#define OFF_XH   (OFF_WH + 96 * WSTRIDE_B)             // 15104
#define OFF_RAWF (OFF_XH + THREADS * XSTRIDE_B)        // 15104+39936 = 55040
#define OFF_RAWP (OFF_RAWF + THREADS * RAWF_STRIDE)    // 55040+49152 = 104192
#define SMEM_TOTAL (OFF_RAWP + THREADS * 16)           // 107264

__device__ float g_A[ENC * D3];
__device__ float g_ybias[D3];

// ---------------- helpers ----------------
__device__ __forceinline__ uint32_t smem_u32(const void* p) {
    uint32_t a;
    asm("{ .reg .u64 t; cvta.to.shared.u64 t, %1; cvt.u32.u64 %0, t; }" : "=r"(a) : "l"(p));
    return a;
}
__device__ __forceinline__ u64 pack2(float lo, float hi) {
    u64 r; asm("mov.b64 %0, {%1, %2};" : "=l"(r) : "f"(lo), "f"(hi)); return r;
}
__device__ __forceinline__ void unpack2(float& lo, float& hi, u64 v) {
    asm("mov.b64 {%0, %1}, %2;" : "=f"(lo), "=f"(hi) : "l"(v));
}
__device__ __forceinline__ u64 ffma2(u64 a, u64 b, u64 c) {
    u64 d; asm("fma.rn.f32x2 %0, %1, %2, %3;" : "=l"(d) : "l"(a), "l"(b), "l"(c)); return d;
}
#define LDSM_X4(r0, r1, r2, r3, a) \
    asm volatile("ldmatrix.sync.aligned.m8n8.x4.shared.b16 {%0,%1,%2,%3}, [%4];" \
                 : "=r"(r0), "=r"(r1), "=r"(r2), "=r"(r3) : "r"(a))
#define LDSM_X4_T(r0, r1, r2, r3, a) \
    asm volatile("ldmatrix.sync.aligned.m8n8.x4.trans.shared.b16 {%0,%1,%2,%3}, [%4];" \
                 : "=r"(r0), "=r"(r1), "=r"(r2), "=r"(r3) : "r"(a))
#define MMA16816H(d, a0, a1, a2, a3, b0, b1) \
    asm volatile("mma.sync.aligned.m16n8k16.row.col.f32.f16.f16.f32 " \
                 "{%0,%1,%2,%3}, {%4,%5,%6,%7}, {%8,%9}, {%0,%1,%2,%3};" \
                 : "+f"((d)[0]), "+f"((d)[1]), "+f"((d)[2]), "+f"((d)[3]) \
                 : "r"(a0), "r"(a1), "r"(a2), "r"(a3), "r"(b0), "r"(b1))
#define CP_ASYNC16(dst, src) \
    asm volatile("cp.async.cg.shared.global [%0], [%1], 16;" :: "r"(dst), "l"(src) : "memory")
#define CP_COMMIT() asm volatile("cp.async.commit_group;" ::: "memory")
#define CP_WAIT0()  asm volatile("cp.async.wait_group 0;" ::: "memory")

__device__ __forceinline__ unsigned pack_h2(float a, float b) {
    __half2 h2 = __floats2half2_rn(a, b);
    return *(unsigned*)&h2;
}

// ---------------------------------------------------------------------------
__global__ void prep_kernel(const float* __restrict__ W2,
                            const float* __restrict__ Wm1,
                            const float* __restrict__ b2,
                            const float* __restrict__ bm1) {
    int t = blockIdx.x * blockDim.x + threadIdx.x;
    if (t < ENC * D3) {
        int k = t >> 6, j = t & 63;
        float s = 0.f;
        #pragma unroll
        for (int e = 0; e < ENC; e++)
            s = fmaf(W2[k * ENC + e], Wm1[e * D3 + j], s);
        g_A[t] = s;
    }
    if (t < D3) {
        float s = bm1[t];
        #pragma unroll
        for (int e = 0; e < ENC; e++)
            s = fmaf(b2[e], Wm1[e * D3 + t], s);
        g_ybias[t] = s;
    }
}

// ---------------------------------------------------------------------------
__global__ __launch_bounds__(THREADS, 2)
void neurtw_mma(const float* __restrict__ pos_table,
                const float* __restrict__ node_feat,
                const float* __restrict__ W1,
                const float* __restrict__ b1,
                const float* __restrict__ Wm1,
                const float* __restrict__ Wm2,
                const float* __restrict__ bm2,
                const int*   __restrict__ key_idx,
                const int*   __restrict__ node_idx,
                float* __restrict__ out,
                int nrows, int ntiles) {
    extern __shared__ __align__(128) char smem[];
    const uint32_t sb = smem_u32(smem);
    const int tid = threadIdx.x, wid = tid >> 5, lane = tid & 31;

    u64*   sW1p  = (u64*)(smem + OFF_W1P);
    u64*   sb1p  = (u64*)(smem + OFF_B1P);
    u64*   sWm2p = (u64*)(smem + OFF_WM2P);
    u64*   sYbp  = (u64*)(smem + OFF_YBP);
    float* sbm2  = (float*)(smem + OFF_BM2);

    if (tid < 32) sWm2p[tid] = pack2(Wm2[2 * tid], Wm2[2 * tid + 1]);
    if (tid >= 32 && tid < 48) { int j = tid - 32; sb1p[j] = pack2(b1[2 * j], b1[2 * j + 1]); }
    if (tid == 48) *sbm2 = bm2[0];
    if (tid >= 64 && tid < 128) {
        int idx = tid - 64, r = idx >> 4, j = idx & 15;
        sW1p[r * 16 + j] = pack2(W1[r * ENC + 2 * j], W1[r * ENC + 2 * j + 1]);
    }
    if (tid >= 128 && tid < 160) {
        int p = tid - 128;
        sYbp[p] = pack2(g_ybias[2 * p], g_ybias[2 * p + 1]);
    }

    // stage W fp16: rows 0..31 g_A, 32..95 Wm1
    for (int t = tid; t < 96 * 64; t += THREADS) {
        int k = t >> 6, n = t & 63;
        float w = (k < ENC) ? g_A[k * D3 + n] : Wm1[k * D3 + n];
        *(__half*)(smem + OFF_WH + k * WSTRIDE_B + n * 2) = __float2half_rn(w);
    }
    __syncthreads();

    // ---- per-lane constant addresses ----
    const int a_row  = (lane & 7) + 8 * ((lane >> 3) & 1);
    const int a_colb = (lane >> 4) * 16;
    const uint32_t xh_base = sb + OFF_XH + (uint32_t)(wid * 32 + a_row) * XSTRIDE_B + a_colb;
    const uint32_t b_off = (uint32_t)(((lane & 7) + 8 * ((lane >> 3) & 1)) * WSTRIDE_B
                                      + (lane >> 4) * 16);
    const uint32_t wh_base = sb + OFF_WH + b_off;

    const int sub = lane >> 4;        // 0..1 : staging/convert row subgroup
    const int qq  = lane & 15;        // 16B chunk within row
    const uint32_t rawf_wbase = sb + OFF_RAWF + (uint32_t)(wid * 32) * RAWF_STRIDE;
    const uint32_t rawp_wbase = sb + OFF_RAWP + (uint32_t)(wid * 32) * 16;

    const int gw0 = blockIdx.x * WARPS + wid;
    const int gwstride = NBLK * WARPS;
    const int g = lane >> 2, q4 = lane & 3;

    // ---- prologue: load first tile's indices and stage via cp.async ----
    int key_c = 0, nid_c = 0;
    if (gw0 < ntiles) {
        int rr = gw0 * 32 + lane; if (rr >= nrows) rr = 0;
        key_c = key_idx[rr]; nid_c = node_idx[rr];
        // pos: lane stages its own row
        CP_ASYNC16(rawp_wbase + lane * 16, (const char*)(pos_table + (size_t)key_c * LP));
        // feat: 16 iterations, lane -> (row 2i+sub, chunk qq)
        #pragma unroll
        for (int i = 0; i < 16; i++) {
            const int riw = 2 * i + sub;
            const int nidr = __shfl_sync(0xffffffffu, nid_c, riw);
            CP_ASYNC16(rawf_wbase + riw * RAWF_STRIDE + qq * 16,
                       (const char*)(node_feat + (size_t)nidr * FEAT) + qq * 16);
        }
        CP_COMMIT();
    }

    for (int tile = gw0; tile < ntiles; tile += gwstride) {
        CP_WAIT0();   // staged data for this tile has landed (each lane reads what it staged)

        // ========== phase 1a: PE hidden layer (packed f32x2) from raw smem ==========
        {
            const float4 e4 = *(const float4*)(smem + OFF_RAWP + (wid * 32 + lane) * 16);
            const u64 ex = pack2(e4.x, e4.x), ey = pack2(e4.y, e4.y);
            const u64 ez = pack2(e4.z, e4.z), ew = pack2(e4.w, e4.w);
            unsigned hv[16];
            #pragma unroll
            for (int j = 0; j < 16; j++) {
                u64 s = sb1p[j];
                s = ffma2(ex, sW1p[0 * 16 + j], s);
                s = ffma2(ey, sW1p[1 * 16 + j], s);
                s = ffma2(ez, sW1p[2 * 16 + j], s);
                s = ffma2(ew, sW1p[3 * 16 + j], s);
                float lo, hi; unpack2(lo, hi, s);
                hv[j] = pack_h2(fmaxf(lo, 0.f), fmaxf(hi, 0.f));
            }
            char* xh = smem + OFF_XH + (wid * 32 + lane) * XSTRIDE_B;
            #pragma unroll
            for (int c = 0; c < 4; c++)
                *(uint4*)(xh + c * 16) =
                    make_uint4(hv[4*c], hv[4*c+1], hv[4*c+2], hv[4*c+3]);
        }
        // ========== phase 1b: convert staged feat (smem->smem) ==========
        {
            #pragma unroll
            for (int i = 0; i < 16; i++) {
                const int riw = 2 * i + sub;
                const float4 fv = *(const float4*)(smem + OFF_RAWF
                                     + (wid * 32 + riw) * RAWF_STRIDE + qq * 16);
                const int off = (wid * 32 + riw) * XSTRIDE_B + 64 + 8 * qq;
                *(uint2*)(smem + OFF_XH + off) =
                    make_uint2(pack_h2(fv.x, fv.y), pack_h2(fv.z, fv.w));
            }
        }
        __syncwarp();

        // ---- load next tile's indices, stage via cp.async (lands during MMA) ----
        {
            const int nt = tile + gwstride;
            if (nt < ntiles) {
                int rr = nt * 32 + lane; if (rr >= nrows) rr = 0;
                key_c = key_idx[rr]; nid_c = node_idx[rr];
                CP_ASYNC16(rawp_wbase + lane * 16, (const char*)(pos_table + (size_t)key_c * LP));
                #pragma unroll
                for (int i = 0; i < 16; i++) {
                    const int riw = 2 * i + sub;
                    const int nidr = __shfl_sync(0xffffffffu, nid_c, riw);
                    CP_ASYNC16(rawf_wbase + riw * RAWF_STRIDE + qq * 16,
                               (const char*)(node_feat + (size_t)nidr * FEAT) + qq * 16);
                }
                CP_COMMIT();
            }
        }

        // ========== phase 2: single-pass fp16 MMA, K=96 ==========
        float acc[2][8][4];
        #pragma unroll
        for (int mt = 0; mt < 2; mt++)
            #pragma unroll
            for (int nt = 0; nt < 8; nt++)
                #pragma unroll
                for (int c = 0; c < 4; c++) acc[mt][nt][c] = 0.f;

        #pragma unroll
        for (int kc = 0; kc < 6; kc++) {
            const uint32_t akoff = (uint32_t)(kc * 32);
            const uint32_t bkoff = (uint32_t)(kc * 16 * WSTRIDE_B);
            uint32_t ah[2][4];
            LDSM_X4(ah[0][0], ah[0][1], ah[0][2], ah[0][3], xh_base + akoff);
            LDSM_X4(ah[1][0], ah[1][1], ah[1][2], ah[1][3], xh_base + 16 * XSTRIDE_B + akoff);

            uint32_t bh[8][2];
            #pragma unroll
            for (int ng = 0; ng < 4; ng++) {
                uint32_t r0, r1, r2, r3;
                LDSM_X4_T(r0, r1, r2, r3, wh_base + bkoff + (uint32_t)(ng * 32));
                bh[2*ng][0] = r0; bh[2*ng][1] = r1; bh[2*ng+1][0] = r2; bh[2*ng+1][1] = r3;
            }
            #pragma unroll
            for (int mt = 0; mt < 2; mt++)
                #pragma unroll
                for (int nt = 0; nt < 8; nt++)
                    MMA16816H(acc[mt][nt], ah[mt][0], ah[mt][1], ah[mt][2], ah[mt][3],
                              bh[nt][0], bh[nt][1]);
        }

        // ========== phase 3: ybias + relu + Wm2 dot (packed), reduce, store ==========
        float zr[4] = {0.f, 0.f, 0.f, 0.f};
        #pragma unroll
        for (int nt = 0; nt < 8; nt++) {
            float y0, y1, w0, w1;
            unpack2(y0, y1, sYbp[nt * 4 + q4]);
            unpack2(w0, w1, sWm2p[nt * 4 + q4]);
            #pragma unroll
            for (int mt = 0; mt < 2; mt++) {
                zr[mt*2+0] = fmaf(fmaxf(acc[mt][nt][0] + y0, 0.f), w0, zr[mt*2+0]);
                zr[mt*2+0] = fmaf(fmaxf(acc[mt][nt][1] + y1, 0.f), w1, zr[mt*2+0]);
                zr[mt*2+1] = fmaf(fmaxf(acc[mt][nt][2] + y0, 0.f), w0, zr[mt*2+1]);
                zr[mt*2+1] = fmaf(fmaxf(acc[mt][nt][3] + y1, 0.f), w1, zr[mt*2+1]);
            }
        }
        #pragma unroll
        for (int o = 1; o < 4; o <<= 1) {
            #pragma unroll
            for (int r = 0; r < 4; r++)
                zr[r] += __shfl_xor_sync(0xffffffffu, zr[r], o);
        }
        if (q4 == 0) {
            const float bias = *sbm2;
            const int base = tile * 32;
            const int rows[4] = {g, g + 8, 16 + g, 24 + g};
            #pragma unroll
            for (int r = 0; r < 4; r++) {
                int orow = base + rows[r];
                if (orow < nrows) out[orow] = zr[r] + bias;
            }
        }
        __syncwarp();
    }
}

// ---------------------------------------------------------------------------
extern "C" void kernel_launch(void* const* d_in, const int* in_sizes, int n_in,
                              void* d_out, int out_size) {
    const float* pos_table = (const float*)d_in[0];
    const float* node_feat = (const float*)d_in[1];
    const float* W1        = (const float*)d_in[2];
    const float* b1        = (const float*)d_in[3];
    const float* W2        = (const float*)d_in[4];
    const float* b2        = (const float*)d_in[5];
    const float* Wm1       = (const float*)d_in[6];
    const float* bm1       = (const float*)d_in[7];
    const float* Wm2       = (const float*)d_in[8];
    const float* bm2       = (const float*)d_in[9];
    const int*   key_idx   = (const int*)d_in[10];
    const int*   node_idx  = (const int*)d_in[11];
    float* out = (float*)d_out;

    const int nrows  = out_size;
    const int ntiles = (nrows + 31) / 32;

    cudaFuncSetAttribute(neurtw_mma,
                         cudaFuncAttributeMaxDynamicSharedMemorySize, SMEM_TOTAL);

    prep_kernel<<<(ENC * D3 + 255) / 256, 256>>>(W2, Wm1, b2, bm1);

    neurtw_mma<<<NBLK, THREADS, SMEM_TOTAL>>>(pos_table, node_feat, W1, b1, Wm1,
                                              Wm2, bm2, key_idx, node_idx, out,
                                              nrows, ntiles);
}

// round 11
// speedup vs baseline: 1.1581x; 1.1028x over previous
#include <cuda_runtime.h>
#include <cuda_fp16.h>
#include <stdint.h>

#define LP    4
#define ENC   32
#define FEAT  64
#define D3    64
#define NBLK  296
#define WARPS 8
#define THREADS (WARPS * 32)

typedef unsigned long long u64;

// X rows (PE only, 32 fp16 = 64 B data): stride 80 B (20 words; 20r mod 32 covers all banks)
#define XSTRIDE_B 80
// W rows: 64 fp16 + pad -> stride 144 B
#define WSTRIDE_B 144
// raw feat rows: 256 B data + 16 B pos (in pad) -> stride 288 B (72 words; 8g-spaced phases)
#define RAWF_STRIDE 288

// ---- smem layout (bytes) ----
#define OFF_W1P  0                                     // 64 u64 (512 B)
#define OFF_B1P  512                                   // 16 u64 (128 B)
#define OFF_WM2P 640                                   // 32 u64 (256 B)
#define OFF_YBP  896                                   // 32 u64 (256 B)
#define OFF_BM2  1152
#define OFF_WH   1280                                  // 96*144 = 13824
#define OFF_XH   (OFF_WH + 96 * WSTRIDE_B)             // 15104; 8*32*80 = 20480
#define OFF_RAWF (OFF_XH + THREADS * XSTRIDE_B)        // 35584; 8*32*288 = 73728
#define SMEM_TOTAL (OFF_RAWF + THREADS * RAWF_STRIDE)  // 109312  (x2 blocks = 218.6 KB/SM)

__device__ float g_A[ENC * D3];
__device__ float g_ybias[D3];

// ---------------- helpers ----------------
__device__ __forceinline__ uint32_t smem_u32(const void* p) {
    uint32_t a;
    asm("{ .reg .u64 t; cvta.to.shared.u64 t, %1; cvt.u32.u64 %0, t; }" : "=r"(a) : "l"(p));
    return a;
}
__device__ __forceinline__ u64 pack2(float lo, float hi) {
    u64 r; asm("mov.b64 %0, {%1, %2};" : "=l"(r) : "f"(lo), "f"(hi)); return r;
}
__device__ __forceinline__ void unpack2(float& lo, float& hi, u64 v) {
    asm("mov.b64 {%0, %1}, %2;" : "=f"(lo), "=f"(hi) : "l"(v));
}
__device__ __forceinline__ u64 ffma2(u64 a, u64 b, u64 c) {
    u64 d; asm("fma.rn.f32x2 %0, %1, %2, %3;" : "=l"(d) : "l"(a), "l"(b), "l"(c)); return d;
}
#define LDSM_X4(r0, r1, r2, r3, a) \
    asm volatile("ldmatrix.sync.aligned.m8n8.x4.shared.b16 {%0,%1,%2,%3}, [%4];" \
                 : "=r"(r0), "=r"(r1), "=r"(r2), "=r"(r3) : "r"(a))
#define LDSM_X4_T(r0, r1, r2, r3, a) \
    asm volatile("ldmatrix.sync.aligned.m8n8.x4.trans.shared.b16 {%0,%1,%2,%3}, [%4];" \
                 : "=r"(r0), "=r"(r1), "=r"(r2), "=r"(r3) : "r"(a))
#define MMA16816H(d, a0, a1, a2, a3, b0, b1) \
    asm volatile("mma.sync.aligned.m16n8k16.row.col.f32.f16.f16.f32 " \
                 "{%0,%1,%2,%3}, {%4,%5,%6,%7}, {%8,%9}, {%0,%1,%2,%3};" \
                 : "+f"((d)[0]), "+f"((d)[1]), "+f"((d)[2]), "+f"((d)[3]) \
                 : "r"(a0), "r"(a1), "r"(a2), "r"(a3), "r"(b0), "r"(b1))
#define CP_ASYNC16(dst, src) \
    asm volatile("cp.async.cg.shared.global [%0], [%1], 16;" :: "r"(dst), "l"(src) : "memory")
#define CP_COMMIT() asm volatile("cp.async.commit_group;" ::: "memory")
#define CP_WAIT0()  asm volatile("cp.async.wait_group 0;" ::: "memory")

__device__ __forceinline__ unsigned pack_h2(float a, float b) {
    __half2 h2 = __floats2half2_rn(a, b);
    return *(unsigned*)&h2;
}

// ---------------------------------------------------------------------------
__global__ void prep_kernel(const float* __restrict__ W2,
                            const float* __restrict__ Wm1,
                            const float* __restrict__ b2,
                            const float* __restrict__ bm1) {
    int t = blockIdx.x * blockDim.x + threadIdx.x;
    if (t < ENC * D3) {
        int k = t >> 6, j = t & 63;
        float s = 0.f;
        #pragma unroll
        for (int e = 0; e < ENC; e++)
            s = fmaf(W2[k * ENC + e], Wm1[e * D3 + j], s);
        g_A[t] = s;
    }
    if (t < D3) {
        float s = bm1[t];
        #pragma unroll
        for (int e = 0; e < ENC; e++)
            s = fmaf(b2[e], Wm1[e * D3 + t], s);
        g_ybias[t] = s;
    }
}

// ---------------------------------------------------------------------------
__global__ __launch_bounds__(THREADS, 2)
void neurtw_mma(const float* __restrict__ pos_table,
                const float* __restrict__ node_feat,
                const float* __restrict__ W1,
                const float* __restrict__ b1,
                const float* __restrict__ Wm1,
                const float* __restrict__ Wm2,
                const float* __restrict__ bm2,
                const int*   __restrict__ key_idx,
                const int*   __restrict__ node_idx,
                float* __restrict__ out,
                int nrows, int ntiles) {
    extern __shared__ __align__(128) char smem[];
    const uint32_t sb = smem_u32(smem);
    const int tid = threadIdx.x, wid = tid >> 5, lane = tid & 31;

    u64*   sW1p  = (u64*)(smem + OFF_W1P);
    u64*   sb1p  = (u64*)(smem + OFF_B1P);
    u64*   sWm2p = (u64*)(smem + OFF_WM2P);
    u64*   sYbp  = (u64*)(smem + OFF_YBP);
    float* sbm2  = (float*)(smem + OFF_BM2);

    if (tid < 32) sWm2p[tid] = pack2(Wm2[2 * tid], Wm2[2 * tid + 1]);
    if (tid >= 32 && tid < 48) { int j = tid - 32; sb1p[j] = pack2(b1[2 * j], b1[2 * j + 1]); }
    if (tid == 48) *sbm2 = bm2[0];
    if (tid >= 64 && tid < 128) {
        int idx = tid - 64, r = idx >> 4, j = idx & 15;
        sW1p[r * 16 + j] = pack2(W1[r * ENC + 2 * j], W1[r * ENC + 2 * j + 1]);
    }
    if (tid >= 128 && tid < 160) {
        int p = tid - 128;
        sYbp[p] = pack2(g_ybias[2 * p], g_ybias[2 * p + 1]);
    }

    // stage W fp16: rows 0..31 g_A, 32..95 Wm1
    for (int t = tid; t < 96 * 64; t += THREADS) {
        int k = t >> 6, n = t & 63;
        float w = (k < ENC) ? g_A[k * D3 + n] : Wm1[k * D3 + n];
        *(__half*)(smem + OFF_WH + k * WSTRIDE_B + n * 2) = __float2half_rn(w);
    }
    __syncthreads();

    // ---- per-lane constant addresses ----
    const int g = lane >> 2, q4 = lane & 3;              // mma row-group / col-in-group
    const int a_row  = (lane & 7) + 8 * ((lane >> 3) & 1);
    const int a_colb = (lane >> 4) * 16;
    const uint32_t xh_base = sb + OFF_XH + (uint32_t)(wid * 32 + a_row) * XSTRIDE_B + a_colb;
    const uint32_t b_off = (uint32_t)(((lane & 7) + 8 * ((lane >> 3) & 1)) * WSTRIDE_B
                                      + (lane >> 4) * 16);
    const uint32_t wh_base = sb + OFF_WH + b_off;

    const int sub = lane >> 4;        // 0..1 staging row subgroup
    const int qq  = lane & 15;        // 16B chunk within row
    const uint32_t rawf_wbase = sb + OFF_RAWF + (uint32_t)(wid * 32) * RAWF_STRIDE;
    // feat A-frag base: rows (mt*16 + g [+8]), cols 16*kcp + 2*q4
    const char* frag_base = smem + OFF_RAWF + (wid * 32 + g) * RAWF_STRIDE + q4 * 8;

    const int gw0 = blockIdx.x * WARPS + wid;
    const int gwstride = NBLK * WARPS;

    // ---- prologue: stage first tile via cp.async ----
    int key_c = 0, nid_c = 0;
    if (gw0 < ntiles) {
        int rr = gw0 * 32 + lane; if (rr >= nrows) rr = 0;
        key_c = key_idx[rr]; nid_c = node_idx[rr];
        CP_ASYNC16(rawf_wbase + lane * RAWF_STRIDE + 256,
                   (const char*)(pos_table + (size_t)key_c * LP));
        #pragma unroll
        for (int i = 0; i < 16; i++) {
            const int riw = 2 * i + sub;
            const int nidr = __shfl_sync(0xffffffffu, nid_c, riw);
            CP_ASYNC16(rawf_wbase + riw * RAWF_STRIDE + qq * 16,
                       (const char*)(node_feat + (size_t)nidr * FEAT) + qq * 16);
        }
        CP_COMMIT();
    }

    for (int tile = gw0; tile < ntiles; tile += gwstride) {
        CP_WAIT0();   // this tile's staged data has landed

        // ========== phase 1a: PE hidden layer (packed f32x2) -> XH fp16 ==========
        {
            const float4 e4 = *(const float4*)(smem + OFF_RAWF
                                  + (wid * 32 + lane) * RAWF_STRIDE + 256);
            const u64 ex = pack2(e4.x, e4.x), ey = pack2(e4.y, e4.y);
            const u64 ez = pack2(e4.z, e4.z), ew = pack2(e4.w, e4.w);
            unsigned hv[16];
            #pragma unroll
            for (int j = 0; j < 16; j++) {
                u64 s = sb1p[j];
                s = ffma2(ex, sW1p[0 * 16 + j], s);
                s = ffma2(ey, sW1p[1 * 16 + j], s);
                s = ffma2(ez, sW1p[2 * 16 + j], s);
                s = ffma2(ew, sW1p[3 * 16 + j], s);
                float lo, hi; unpack2(lo, hi, s);
                hv[j] = pack_h2(fmaxf(lo, 0.f), fmaxf(hi, 0.f));
            }
            char* xh = smem + OFF_XH + (wid * 32 + lane) * XSTRIDE_B;
            *(uint4*)(xh)      = make_uint4(hv[0], hv[1], hv[2],  hv[3]);
            *(uint4*)(xh + 16) = make_uint4(hv[4], hv[5], hv[6],  hv[7]);
            *(uint4*)(xh + 32) = make_uint4(hv[8], hv[9], hv[10], hv[11]);
            *(uint4*)(xh + 48) = make_uint4(hv[12],hv[13],hv[14], hv[15]);
        }

        // ========== phase 1b: build feat A-fragments from raw fp32 smem ==========
        // m16n8k16 A layout: a0=(g,c|c+1) a1=(g+8,..) a2=(g,c+8|c+9) a3=(g+8,c+8|c+9)
        uint32_t af[4][2][4];
        #pragma unroll
        for (int kcp = 0; kcp < 4; kcp++) {
            #pragma unroll
            for (int mt = 0; mt < 2; mt++) {
                const char* p = frag_base + mt * 16 * RAWF_STRIDE + kcp * 64;
                float2 v;
                v = *(const float2*)(p);                         af[kcp][mt][0] = pack_h2(v.x, v.y);
                v = *(const float2*)(p + 8 * RAWF_STRIDE);       af[kcp][mt][1] = pack_h2(v.x, v.y);
                v = *(const float2*)(p + 32);                    af[kcp][mt][2] = pack_h2(v.x, v.y);
                v = *(const float2*)(p + 8 * RAWF_STRIDE + 32);  af[kcp][mt][3] = pack_h2(v.x, v.y);
            }
        }
        __syncwarp();   // XH STS visible to warp before ldmatrix; RAWF fully consumed

        // ---- stage next tile (lands during MMA + epilogue) ----
        {
            const int nt = tile + gwstride;
            if (nt < ntiles) {
                int rr = nt * 32 + lane; if (rr >= nrows) rr = 0;
                key_c = key_idx[rr]; nid_c = node_idx[rr];
                CP_ASYNC16(rawf_wbase + lane * RAWF_STRIDE + 256,
                           (const char*)(pos_table + (size_t)key_c * LP));
                #pragma unroll
                for (int i = 0; i < 16; i++) {
                    const int riw = 2 * i + sub;
                    const int nidr = __shfl_sync(0xffffffffu, nid_c, riw);
                    CP_ASYNC16(rawf_wbase + riw * RAWF_STRIDE + qq * 16,
                               (const char*)(node_feat + (size_t)nidr * FEAT) + qq * 16);
                }
                CP_COMMIT();
            }
        }

        // ========== phase 2: single-pass fp16 MMA, K=96 ==========
        float acc[2][8][4];
        #pragma unroll
        for (int mt = 0; mt < 2; mt++)
            #pragma unroll
            for (int nt = 0; nt < 8; nt++)
                #pragma unroll
                for (int c = 0; c < 4; c++) acc[mt][nt][c] = 0.f;

        #pragma unroll
        for (int kc = 0; kc < 6; kc++) {
            const uint32_t bkoff = (uint32_t)(kc * 16 * WSTRIDE_B);
            uint32_t ah[2][4];
            if (kc < 2) {                       // PE columns via ldmatrix
                const uint32_t akoff = (uint32_t)(kc * 32);
                LDSM_X4(ah[0][0], ah[0][1], ah[0][2], ah[0][3], xh_base + akoff);
                LDSM_X4(ah[1][0], ah[1][1], ah[1][2], ah[1][3],
                        xh_base + 16 * XSTRIDE_B + akoff);
            } else {                            // feat columns from parked fragments
                #pragma unroll
                for (int mt = 0; mt < 2; mt++)
                    #pragma unroll
                    for (int c = 0; c < 4; c++) ah[mt][c] = af[kc - 2][mt][c];
            }

            uint32_t bh[8][2];
            #pragma unroll
            for (int ng = 0; ng < 4; ng++) {
                uint32_t r0, r1, r2, r3;
                LDSM_X4_T(r0, r1, r2, r3, wh_base + bkoff + (uint32_t)(ng * 32));
                bh[2*ng][0] = r0; bh[2*ng][1] = r1; bh[2*ng+1][0] = r2; bh[2*ng+1][1] = r3;
            }
            #pragma unroll
            for (int mt = 0; mt < 2; mt++)
                #pragma unroll
                for (int nt = 0; nt < 8; nt++)
                    MMA16816H(acc[mt][nt], ah[mt][0], ah[mt][1], ah[mt][2], ah[mt][3],
                              bh[nt][0], bh[nt][1]);
        }

        // ========== phase 3: ybias + relu + Wm2 dot (packed), reduce, store ==========
        float zr[4] = {0.f, 0.f, 0.f, 0.f};
        #pragma unroll
        for (int nt = 0; nt < 8; nt++) {
            float y0, y1, w0, w1;
            unpack2(y0, y1, sYbp[nt * 4 + q4]);
            unpack2(w0, w1, sWm2p[nt * 4 + q4]);
            #pragma unroll
            for (int mt = 0; mt < 2; mt++) {
                zr[mt*2+0] = fmaf(fmaxf(acc[mt][nt][0] + y0, 0.f), w0, zr[mt*2+0]);
                zr[mt*2+0] = fmaf(fmaxf(acc[mt][nt][1] + y1, 0.f), w1, zr[mt*2+0]);
                zr[mt*2+1] = fmaf(fmaxf(acc[mt][nt][2] + y0, 0.f), w0, zr[mt*2+1]);
                zr[mt*2+1] = fmaf(fmaxf(acc[mt][nt][3] + y1, 0.f), w1, zr[mt*2+1]);
            }
        }
        #pragma unroll
        for (int o = 1; o < 4; o <<= 1) {
            #pragma unroll
            for (int r = 0; r < 4; r++)
                zr[r] += __shfl_xor_sync(0xffffffffu, zr[r], o);
        }
        if (q4 == 0) {
            const float bias = *sbm2;
            const int base = tile * 32;
            const int rows[4] = {g, g + 8, 16 + g, 24 + g};
            #pragma unroll
            for (int r = 0; r < 4; r++) {
                int orow = base + rows[r];
                if (orow < nrows) out[orow] = zr[r] + bias;
            }
        }
        __syncwarp();
    }
}

// ---------------------------------------------------------------------------
extern "C" void kernel_launch(void* const* d_in, const int* in_sizes, int n_in,
                              void* d_out, int out_size) {
    const float* pos_table = (const float*)d_in[0];
    const float* node_feat = (const float*)d_in[1];
    const float* W1        = (const float*)d_in[2];
    const float* b1        = (const float*)d_in[3];
    const float* W2        = (const float*)d_in[4];
    const float* b2        = (const float*)d_in[5];
    const float* Wm1       = (const float*)d_in[6];
    const float* bm1       = (const float*)d_in[7];
    const float* Wm2       = (const float*)d_in[8];
    const float* bm2       = (const float*)d_in[9];
    const int*   key_idx   = (const int*)d_in[10];
    const int*   node_idx  = (const int*)d_in[11];
    float* out = (float*)d_out;

    const int nrows  = out_size;
    const int ntiles = (nrows + 31) / 32;

    cudaFuncSetAttribute(neurtw_mma,
                         cudaFuncAttributeMaxDynamicSharedMemorySize, SMEM_TOTAL);

    prep_kernel<<<(ENC * D3 + 255) / 256, 256>>>(W2, Wm1, b2, bm1);

    neurtw_mma<<<NBLK, THREADS, SMEM_TOTAL>>>(pos_table, node_feat, W1, b1, Wm1,
                                              Wm2, bm2, key_idx, node_idx, out,
                                              nrows, ntiles);
}